// round 5
// baseline (speedup 1.0000x reference)
#include <cuda_runtime.h>

// SIR recurrence, round 4.
// Serial loop is the irreducible core only: 5 FMA-class ops + ONE STS.32/iter.
//     m     = s0 * s2
//     inner = fma(K, s0, B)       pre = s2 - B        (off-chain)
//     s0'   = fma( A, m, inner)   s2' = fma(-A, m, pre)
// Only s0 is staged (contiguous). Everything else is reconstructed in parallel:
//     Q_i   = prefix sum of s0-out
//     s1[i] = fma(w2^2, x0 + Q_{i-1}, x1)
//     s3[i] = fma(w4^2, x0 + Q_{i-1}, x3)
//     s2[i] = (x2 + K*x0) - s0[i] - (1-K)*Q_{i-1}     (telescoped c-sum)
// Final phase: fully coalesced elementwise GMEM write, no staging buffer.

#define MAX_STEPS 2048

__global__ void __launch_bounds__(256, 1)
sir_kernel(const float* __restrict__ x,
           const float* __restrict__ w2p,
           const float* __restrict__ w3p,
           const float* __restrict__ b3p,
           const float* __restrict__ w4p,
           float* __restrict__ out,
           int n)
{
    __shared__ float s0buf[MAX_STEPS];   // s0-out per step (stride-1 staging)
    __shared__ float Qarr[MAX_STEPS];    // inclusive prefix of s0buf
    __shared__ float wsum[8];

    const int tid   = threadIdx.x;
    const int steps = n - 1;             // 2047
    const int total = steps * 5;

    const float w2 = *w2p, w3 = *w3p, b3 = *b3p, w4 = *w4p;
    const float w2sq = w2 * w2;
    const float w4sq = w4 * w4;
    const float K    = 1.0f - w2sq - w4sq;
    const float A    = w3 * w3 * 1.0e-3f;
    const float B    = fmaf(w3, b3, b3);

    // ---- Phase 1: serial recurrence on thread 0 (chain-bound) ----
    if (tid == 0) {
        float s0 = x[0], s2 = x[2];
        const float negA = -A;
        float* p = s0buf;
        #pragma unroll 16
        for (int i = 0; i < steps; ++i) {
            const float m     = s0 * s2;              // chain
            const float inner = fmaf(K, s0, B);       // off-chain (old s0)
            const float pre   = s2 - B;               // off-chain (old s2)
            s0 = fmaf(A,    m, inner);                // chain
            s2 = fmaf(negA, m, pre);                  // chain
            p[i] = s0;                                // single STS.32, imm offset
        }
    }
    __syncthreads();

    // ---- Phase 2: block-wide inclusive prefix of s0buf -> Qarr ----
    {
        const int base = tid * 8;
        float loc[8];
        float run = 0.0f;
        #pragma unroll
        for (int k = 0; k < 8; ++k) {
            const int r = base + k;
            const float v = (r < steps) ? s0buf[r] : 0.0f;
            run += v;
            loc[k] = run;
        }

        const unsigned lane = tid & 31u;
        const unsigned wid  = tid >> 5;
        float scan = run;
        #pragma unroll
        for (int off = 1; off < 32; off <<= 1) {
            const float o = __shfl_up_sync(0xffffffffu, scan, off);
            if (lane >= off) scan += o;
        }
        if (lane == 31) wsum[wid] = scan;
        __syncthreads();

        float woff = 0.0f;
        #pragma unroll
        for (unsigned w = 0; w < 8; ++w)
            if (w < wid) woff += wsum[w];

        const float texcl = woff + (scan - run);   // sum of all rows before base
        #pragma unroll
        for (int k = 0; k < 8; ++k) {
            const int r = base + k;
            if (r < steps) Qarr[r] = texcl + loc[k];
        }
    }
    __syncthreads();

    // ---- Phase 3: coalesced elementwise output ----
    {
        const float x0 = x[0], x1 = x[1], x3 = x[3];
        const float base2 = x[2] + K * x0;         // x2 + K*x0
        const float oneK  = w2sq + w4sq;           // 1 - K

        for (int i = tid; i < total; i += 256) {
            const int ro = i / 5;                  // output row (step ro+1)
            const int j  = i - ro * 5;
            const float s0v  = s0buf[ro];
            const float Qexc = (ro > 0) ? Qarr[ro - 1] : 0.0f;
            float v;
            if (j == 0)      v = s0v;
            else if (j == 1) v = fmaf(w2sq, x0 + Qexc, x1);
            else if (j == 2) v = fmaf(-oneK, Qexc, base2 - s0v);
            else if (j == 3) v = fmaf(w4sq, x0 + Qexc, x3);
            else             v = 0.0f;
            out[i] = v;
        }
    }
}

extern "C" void kernel_launch(void* const* d_in, const int* in_sizes, int n_in,
                              void* d_out, int out_size)
{
    const float* x  = (const float*)d_in[0];
    const float* w2 = (const float*)d_in[1];
    const float* w3 = (const float*)d_in[2];
    const float* b3 = (const float*)d_in[3];
    const float* w4 = (const float*)d_in[4];
    float* out = (float*)d_out;

    const int n = out_size / 5 + 1;   // out_size = (n-1)*5

    sir_kernel<<<1, 256>>>(x, w2, w3, b3, w4, out, n);
}

// round 8
// speedup vs baseline: 1.2615x; 1.2615x over previous
#include <cuda_runtime.h>

// SIR recurrence, round 5: producer/consumer pipeline in one block.
//
// Warp 0, lane 0 runs the irreducible serial chain (5 FMA-class ops + 1 STS):
//     m   = s0 * s2
//     s0' = fma( A, m, fma(K, s0, B))
//     s2' = fma(-A, m, s2 - B)
// in 4 chunks of 672 steps, arriving at named barrier (c+1) after each chunk.
//
// Warps 1..7 (224 threads) bar.sync on each chunk barrier, then — concurrent
// with the producer's NEXT chunk — scan the chunk's s0 values and emit all 5
// output slots per row directly to GMEM:
//     Q    = prefix sum of s0-out (exact via chunk carry)
//     s1_r = fma(w2^2, x0 + Qexc, x1)
//     s3_r = fma(w4^2, x0 + Qexc, x3)
//     s2_r = (x2 + K*x0) - s0_r - (1-K)*Qexc      (telescoped c-sum, R4-proven)
//     slot4 = 0
// Only the last chunk's (31-row) processing is exposed after the serial loop.

#define CH        672            // 224 consumer threads * 3 rows
#define NCH       4              // ceil(2047 / 672)
#define MAX_STEPS 2048

#define NB_ARRIVE(id, cnt) \
    asm volatile("bar.arrive %0, %1;" :: "r"(id), "r"(cnt) : "memory")
#define NB_SYNC(id, cnt) \
    asm volatile("bar.sync %0, %1;" :: "r"(id), "r"(cnt) : "memory")

__global__ void __launch_bounds__(256, 1)
sir_kernel(const float* __restrict__ x,
           const float* __restrict__ w2p,
           const float* __restrict__ w3p,
           const float* __restrict__ b3p,
           const float* __restrict__ w4p,
           float* __restrict__ out,
           int n)
{
    __shared__ float s0buf[MAX_STEPS];
    __shared__ float wpart[8];          // consumer per-warp scan partials

    const int tid   = threadIdx.x;
    const int steps = n - 1;            // 2047

    const float w2 = *w2p, w3 = *w3p, b3 = *b3p, w4 = *w4p;
    const float w2sq = w2 * w2;
    const float w4sq = w4 * w4;
    const float K    = 1.0f - w2sq - w4sq;
    const float A    = w3 * w3 * 1.0e-3f;
    const float B    = fmaf(w3, b3, b3);

    if (tid < 32) {
        // ---------------- producer: warp 0 ----------------
        float s0 = x[0], s2 = x[2];
        const float negA = -A;
        float* p = s0buf;

        int done = 0;
        for (int c = 0; c < NCH; ++c) {
            const int end = (done + CH < steps) ? done + CH : steps;
            if (tid == 0) {
                #pragma unroll 8
                for (int i = done; i < end; ++i) {
                    const float m     = s0 * s2;             // chain
                    const float inner = fmaf(K, s0, B);      // off-chain
                    const float pre   = s2 - B;              // off-chain
                    s0 = fmaf(A,    m, inner);               // chain
                    s2 = fmaf(negA, m, pre);                 // chain
                    p[i] = s0;                               // STS.32
                }
            }
            done = end;
            __syncwarp();
            NB_ARRIVE(c + 1, 256);       // release consumers for chunk c
        }
    } else {
        // ---------------- consumers: warps 1..7 (224 threads) ----------------
        const int      ctid = tid - 32;          // 0..223
        const int      cw   = ctid >> 5;         // consumer warp 0..6
        const unsigned lane = tid & 31u;

        const float x0 = x[0], x1 = x[1], x3 = x[3];
        const float base2 = x[2] + K * x0;       // x2 + K*x0
        const float oneK  = w2sq + w4sq;         // 1 - K

        float carry = 0.0f;                      // sum of s0 over prior chunks

        for (int c = 0; c < NCH; ++c) {
            NB_SYNC(c + 1, 256);                 // wait for producer chunk c

            const int r0 = c * CH + ctid * 3;    // first of this thread's 3 rows
            float v0 = (r0     < steps) ? s0buf[r0]     : 0.0f;
            float v1 = (r0 + 1 < steps) ? s0buf[r0 + 1] : 0.0f;
            float v2 = (r0 + 2 < steps) ? s0buf[r0 + 2] : 0.0f;

            const float l1  = v0 + v1;
            const float run = l1 + v2;           // thread total

            // inclusive warp scan of per-thread totals
            float scan = run;
            #pragma unroll
            for (int off = 1; off < 32; off <<= 1) {
                const float o = __shfl_up_sync(0xffffffffu, scan, off);
                if (lane >= off) scan += o;
            }
            if (lane == 31) wpart[cw] = scan;
            NB_SYNC(15, 224);                    // consumer-internal sync

            float woff = 0.0f, chtot = 0.0f;
            #pragma unroll
            for (int w = 0; w < 7; ++w) {
                const float pv = wpart[w];
                chtot += pv;
                if (w < cw) woff += pv;
            }

            // exclusive prefix of s0-out before row r0 (global, exact)
            float Qexc = carry + woff + (scan - run);

            #pragma unroll
            for (int k = 0; k < 3; ++k) {
                const int r = r0 + k;
                const float s0v = (k == 0) ? v0 : (k == 1) ? v1 : v2;
                if (r < steps) {
                    const float S = x0 + Qexc;
                    float* o = out + 5 * r;
                    o[0] = s0v;
                    o[1] = fmaf(w2sq, S, x1);
                    o[2] = fmaf(-oneK, Qexc, base2 - s0v);
                    o[3] = fmaf(w4sq, S, x3);
                    o[4] = 0.0f;
                }
                Qexc += s0v;
            }

            carry += chtot;
            // NOTE: no extra barrier needed before next chunk — every consumer's
            // wpart reads happen before it arrives at barrier c+2, which releases
            // only after all consumers (and the producer) arrive.
        }
    }
}

extern "C" void kernel_launch(void* const* d_in, const int* in_sizes, int n_in,
                              void* d_out, int out_size)
{
    const float* x  = (const float*)d_in[0];
    const float* w2 = (const float*)d_in[1];
    const float* w3 = (const float*)d_in[2];
    const float* b3 = (const float*)d_in[3];
    const float* w4 = (const float*)d_in[4];
    float* out = (float*)d_out;

    const int n = out_size / 5 + 1;   // out_size = (n-1)*5

    sir_kernel<<<1, 256>>>(x, w2, w3, b3, w4, out, n);
}